// round 14
// baseline (speedup 1.0000x reference)
#include <cuda_runtime.h>
#include <cuda_bf16.h>
#include <cstdint>

#define F 128
#define RCUT 5.0f
#define MAX_NODES 100000
#define NODE_GRID 296

// Scratch (allocation-free rule: __device__ globals)
__device__ float  q_dev[MAX_NODES];
__device__ float4 mu4_dev[MAX_NODES];
// Transposed split-bf16 W1 images: W1T[f][k], dense [128][128] bf16
__device__ __align__(16) unsigned char W1T_hi[32768];
__device__ __align__(16) unsigned char W1T_lo[32768];

static __device__ __forceinline__ float silu_f(float z) {
    return __fdividef(z, 1.0f + __expf(-z));
}
static __device__ __forceinline__ uint32_t bpack(__nv_bfloat16 lo, __nv_bfloat16 hi) {
    return (uint32_t)__bfloat16_as_ushort(lo) | ((uint32_t)__bfloat16_as_ushort(hi) << 16);
}
static __device__ __forceinline__ uint32_t smem_u32(const void* p) {
    uint32_t a;
    asm("{ .reg .u64 t; cvta.to.shared.u64 t, %1; cvt.u32.u64 %0, t; }" : "=r"(a) : "l"(p));
    return a;
}

// warp-level bf16 MMA, baseline ISA (works on plain sm_103 target)
static __device__ __forceinline__ void mma16816(float* d, const uint32_t* a,
                                                uint32_t b0, uint32_t b1) {
    asm volatile(
        "mma.sync.aligned.m16n8k16.row.col.f32.bf16.bf16.f32 "
        "{%0,%1,%2,%3}, {%4,%5,%6,%7}, {%8,%9}, {%0,%1,%2,%3};"
        : "+f"(d[0]), "+f"(d[1]), "+f"(d[2]), "+f"(d[3])
        : "r"(a[0]), "r"(a[1]), "r"(a[2]), "r"(a[3]), "r"(b0), "r"(b1));
}
static __device__ __forceinline__ void ldsm4(uint32_t* r, uint32_t addr) {
    asm volatile("ldmatrix.sync.aligned.m8n8.x4.shared.b16 {%0,%1,%2,%3}, [%4];"
                 : "=r"(r[0]), "=r"(r[1]), "=r"(r[2]), "=r"(r[3]) : "r"(addr));
}
// 3-word atomic add: v2 on (x,y), scalar on z — skips the wasted w-word
static __device__ __forceinline__ void red_xyz(float4* addr, float vx, float vy, float vz) {
    asm volatile("red.global.add.v2.f32 [%0], {%1, %2};"
                 :: "l"((float*)addr), "f"(vx), "f"(vy) : "memory");
    asm volatile("red.global.add.f32 [%0], %1;"
                 :: "l"(((float*)addr) + 2), "f"(vz) : "memory");
}

// ---------- Kernel 0: W1 -> transposed split-bf16 images ----------
__global__ void prep_B_kernel(const float* __restrict__ W1) {
    const int f = threadIdx.x;
    const int b = blockIdx.x;
    uint32_t hi[4], lo[4];
    #pragma unroll
    for (int j = 0; j < 4; j++) {
        const float w0 = W1[(8 * b + 2 * j)     * F + f];
        const float w1 = W1[(8 * b + 2 * j + 1) * F + f];
        const __nv_bfloat16 h0 = __float2bfloat16_rn(w0);
        const __nv_bfloat16 h1 = __float2bfloat16_rn(w1);
        const __nv_bfloat16 l0 = __float2bfloat16_rn(w0 - __bfloat162float(h0));
        const __nv_bfloat16 l1 = __float2bfloat16_rn(w1 - __bfloat162float(h1));
        hi[j] = bpack(h0, h1);
        lo[j] = bpack(l0, l1);
    }
    *(uint4*)(W1T_hi + f * 256 + b * 16) = make_uint4(hi[0], hi[1], hi[2], hi[3]);
    *(uint4*)(W1T_lo + f * 256 + b * 16) = make_uint4(lo[0], lo[1], lo[2], lo[3]);
}

// ---------- Kernel 1: persistent node MLP, pipelined split-bf16 mma.sync ----
#define PADB 272
#define SM_AH  0
#define SM_AL  17408
#define SM_BH  34816
#define SM_BL  69632
#define SM_B1  104448
#define SM_W2  104960
#define SM_RED 105472
#define SM_TOT 106496

static __device__ __forceinline__ void load_xtile(float4* xreg, const float* __restrict__ x,
                                                  int tile, int n_tiles, int n_nodes, int tid) {
    const int base = tile * 64;
    #pragma unroll
    for (int j = 0; j < 8; j++) {
        const int i   = tid + j * 256;
        const int row = i >> 5;
        const int c4  = i & 31;
        xreg[j] = make_float4(0.f, 0.f, 0.f, 0.f);
        if (tile < n_tiles && base + row < n_nodes)
            xreg[j] = ((const float4*)(x + (size_t)(base + row) * F))[c4];
    }
}
static __device__ __forceinline__ void store_xtile(unsigned char* smem, const float4* xreg,
                                                   int tid) {
    #pragma unroll
    for (int j = 0; j < 8; j++) {
        const int i   = tid + j * 256;
        const int row = i >> 5;
        const int col = 4 * (i & 31);
        const float4 v = xreg[j];
        const __nv_bfloat16 h0 = __float2bfloat16_rn(v.x);
        const __nv_bfloat16 h1 = __float2bfloat16_rn(v.y);
        const __nv_bfloat16 h2 = __float2bfloat16_rn(v.z);
        const __nv_bfloat16 h3 = __float2bfloat16_rn(v.w);
        const __nv_bfloat16 l0 = __float2bfloat16_rn(v.x - __bfloat162float(h0));
        const __nv_bfloat16 l1 = __float2bfloat16_rn(v.y - __bfloat162float(h1));
        const __nv_bfloat16 l2 = __float2bfloat16_rn(v.z - __bfloat162float(h2));
        const __nv_bfloat16 l3 = __float2bfloat16_rn(v.w - __bfloat162float(h3));
        const int off = row * PADB + col * 2;
        *(uint2*)(smem + SM_AH + off) = make_uint2(bpack(h0, h1), bpack(h2, h3));
        *(uint2*)(smem + SM_AL + off) = make_uint2(bpack(l0, l1), bpack(l2, l3));
    }
}

__global__ void __launch_bounds__(256, 2)
node_q_kernel(const float* __restrict__ x, const float* __restrict__ b1,
              const float* __restrict__ W2, const float* __restrict__ b2,
              int n_nodes) {
    extern __shared__ __align__(16) unsigned char smem[];
    const uint32_t sb = smem_u32(smem);
    const int tid  = threadIdx.x;
    const int wid  = tid >> 5;
    const int lane = tid & 31;
    const int g    = lane >> 2;
    const int qp   = lane & 3;
    const int mi   = wid & 1;     // 32-node subtile
    const int nj   = wid >> 1;    // 32-feature subtile
    const int n_tiles = (n_nodes + 63) / 64;

    // Zero accumulation scratch (edge kernel is ordered after us)
    for (int i = blockIdx.x * 256 + tid; i < n_nodes; i += NODE_GRID * 256)
        mu4_dev[i] = make_float4(0.f, 0.f, 0.f, 0.f);

    // ---- Stage B images ONCE per CTA ----
    for (int i = tid; i < 4096; i += 256) {
        const int row = i >> 5;
        const int c4  = i & 31;
        const int goff = row * 256 + c4 * 8;
        const int soff = row * PADB + c4 * 8;
        *(uint2*)(smem + SM_BH + soff) = *(const uint2*)(W1T_hi + goff);
        *(uint2*)(smem + SM_BL + soff) = *(const uint2*)(W1T_lo + goff);
    }
    if (tid < 128) {
        ((float*)(smem + SM_B1))[tid] = b1[tid];
        ((float*)(smem + SM_W2))[tid] = W2[tid];
    }

    // ldmatrix per-thread offsets
    const int lr = lane & 7;
    const uint32_t aoff = (uint32_t)(32 * mi + lr + 8 * ((lane >> 3) & 1)) * PADB
                        + 16 * (lane >> 4);
    const uint32_t boff = (uint32_t)(32 * nj + lr + 8 * (lane >> 4)) * PADB
                        + 16 * ((lane >> 3) & 1);

    const float* b1s = (const float*)(smem + SM_B1);
    const float* w2s = (const float*)(smem + SM_W2);
    float* red = (float*)(smem + SM_RED);   // [4 nj][64 rows]
    const float b2v = b2[0];

    // ---- Pipeline prologue ----
    float4 xreg[8];
    int t = blockIdx.x;
    load_xtile(xreg, x, t, n_tiles, n_nodes, tid);
    store_xtile(smem, xreg, tid);
    load_xtile(xreg, x, t + NODE_GRID, n_tiles, n_nodes, tid);
    __syncthreads();

    for (; t < n_tiles; t += NODE_GRID) {
        // ---- Fused 3-term MMA over current A tile ----
        float acc[2][4][4];
        #pragma unroll
        for (int mc = 0; mc < 2; mc++)
            #pragma unroll
            for (int nc = 0; nc < 4; nc++)
                #pragma unroll
                for (int r = 0; r < 4; r++) acc[mc][nc][r] = 0.0f;

        #pragma unroll
        for (int kc = 0; kc < 8; kc++) {
            const uint32_t kb = kc * 32;
            uint32_t ah[2][4], al[2][4];
            ldsm4(ah[0], sb + SM_AH + aoff + kb);
            ldsm4(ah[1], sb + SM_AH + aoff + 16 * PADB + kb);
            ldsm4(al[0], sb + SM_AL + aoff + kb);
            ldsm4(al[1], sb + SM_AL + aoff + 16 * PADB + kb);
            #pragma unroll
            for (int c = 0; c < 2; c++) {
                uint32_t bh[4], bl[4];
                ldsm4(bh, sb + SM_BH + boff + c * 16 * PADB + kb);
                ldsm4(bl, sb + SM_BL + boff + c * 16 * PADB + kb);
                #pragma unroll
                for (int h = 0; h < 2; h++) {
                    const int nc = 2 * c + h;
                    #pragma unroll
                    for (int mc = 0; mc < 2; mc++) {
                        mma16816(acc[mc][nc], ah[mc], bh[2 * h], bh[2 * h + 1]); // xh@Wh
                        mma16816(acc[mc][nc], al[mc], bh[2 * h], bh[2 * h + 1]); // xl@Wh
                        mma16816(acc[mc][nc], ah[mc], bl[2 * h], bl[2 * h + 1]); // xh@Wl
                    }
                }
            }
        }

        // ---- Epilogue: partial q over this warp's 32 features ----
        #pragma unroll
        for (int mc = 0; mc < 2; mc++) {
            #pragma unroll
            for (int rh = 0; rh < 2; rh++) {
                float s = 0.0f;
                #pragma unroll
                for (int nc = 0; nc < 4; nc++) {
                    const int f0 = 32 * nj + 8 * nc + 2 * qp;
                    const float h0 = acc[mc][nc][2 * rh]     + b1s[f0];
                    const float h1 = acc[mc][nc][2 * rh + 1] + b1s[f0 + 1];
                    s += silu_f(h0) * w2s[f0] + silu_f(h1) * w2s[f0 + 1];
                }
                s += __shfl_xor_sync(0xffffffffu, s, 1);
                s += __shfl_xor_sync(0xffffffffu, s, 2);
                if (qp == 0)
                    red[nj * 64 + 32 * mi + 16 * mc + 8 * rh + g] = s;
            }
        }
        __syncthreads();   // red ready; all warps done reading A
        const int base = t * 64;
        if (tid < 64 && base + tid < n_nodes) {
            const float sum = (red[tid] + red[64 + tid]) + (red[128 + tid] + red[192 + tid]);
            q_dev[base + tid] = silu_f(sum + b2v);
        }

        // ---- Stage next tile (regs -> smem), prefetch tile after next ----
        store_xtile(smem, xreg, tid);
        load_xtile(xreg, x, t + 2 * NODE_GRID, n_tiles, n_nodes, tid);
        __syncthreads();   // A(t+G) ready; red consumed
    }
}

// ---------- Kernel 2: edge pass, 4 edges/thread; 3-word REDs (v2 + scalar) --
__global__ void __launch_bounds__(256)
edge_kernel4(const float4* __restrict__ rij4, const float4* __restrict__ vij4,
             const int4* __restrict__ src4, const int4* __restrict__ dst4,
             int n_quads) {
    const int i = blockIdx.x * blockDim.x + threadIdx.x;
    if (i >= n_quads) return;

    const float4 r = rij4[i];
    const int4   s = src4[i];
    const int4   d = dst4[i];
    const float4 a = vij4[(size_t)3 * i];
    const float4 b = vij4[(size_t)3 * i + 1];
    const float4 c = vij4[(size_t)3 * i + 2];

    const float k = 3.14159265358979323846f / RCUT;
    float c0 = 0.5f * (__cosf(r.x * k) + 1.0f); if (r.x >= RCUT) c0 = 0.0f;
    float c1 = 0.5f * (__cosf(r.y * k) + 1.0f); if (r.y >= RCUT) c1 = 0.0f;
    float c2 = 0.5f * (__cosf(r.z * k) + 1.0f); if (r.z >= RCUT) c2 = 0.0f;
    float c3 = 0.5f * (__cosf(r.w * k) + 1.0f); if (r.w >= RCUT) c3 = 0.0f;

    const float s0 = __ldg(&q_dev[s.x]) * c0;
    const float s1 = __ldg(&q_dev[s.y]) * c1;
    const float s2 = __ldg(&q_dev[s.z]) * c2;
    const float s3 = __ldg(&q_dev[s.w]) * c3;

    red_xyz(&mu4_dev[d.x], a.x * s0, a.y * s0, a.z * s0);
    red_xyz(&mu4_dev[d.y], a.w * s1, b.x * s1, b.y * s1);
    red_xyz(&mu4_dev[d.z], b.z * s2, b.w * s2, c.x * s2);
    red_xyz(&mu4_dev[d.w], c.y * s3, c.z * s3, c.w * s3);
}

// ---------- Kernel 3: compact [N,4] scratch -> [N,3] output, 4 nodes/thread --
__global__ void copy_kernel4(float4* __restrict__ out4, int n_quads) {
    const int i = blockIdx.x * blockDim.x + threadIdx.x;
    if (i >= n_quads) return;
    const float4 m0 = mu4_dev[4 * i];
    const float4 m1 = mu4_dev[4 * i + 1];
    const float4 m2 = mu4_dev[4 * i + 2];
    const float4 m3 = mu4_dev[4 * i + 3];
    out4[3 * i]     = make_float4(m0.x, m0.y, m0.z, m1.x);
    out4[3 * i + 1] = make_float4(m1.y, m1.z, m2.x, m2.y);
    out4[3 * i + 2] = make_float4(m2.z, m3.x, m3.y, m3.z);
}

extern "C" void kernel_launch(void* const* d_in, const int* in_sizes, int n_in,
                              void* d_out, int out_size) {
    const float* x   = (const float*)d_in[0];
    const float* rij = (const float*)d_in[1];
    const float* vij = (const float*)d_in[2];
    const int*   src = (const int*)d_in[3];
    const int*   dst = (const int*)d_in[4];
    const float* W1  = (const float*)d_in[5];
    const float* b1  = (const float*)d_in[6];
    const float* W2  = (const float*)d_in[7];
    const float* b2  = (const float*)d_in[8];
    float* out = (float*)d_out;

    const int n_nodes = in_sizes[0] / F;   // 100000
    const int n_edges = in_sizes[1];       // 6400000

    cudaFuncSetAttribute(node_q_kernel,
                         cudaFuncAttributeMaxDynamicSharedMemorySize, SM_TOT);

    prep_B_kernel<<<16, 128>>>(W1);

    node_q_kernel<<<NODE_GRID, 256, SM_TOT>>>(x, b1, W2, b2, n_nodes);

    const int eq = n_edges / 4;            // 1,600,000 (exact)
    edge_kernel4<<<(eq + 255) / 256, 256>>>((const float4*)rij, (const float4*)vij,
                                            (const int4*)src, (const int4*)dst, eq);

    const int nq = n_nodes / 4;            // 25,000 (exact)
    copy_kernel4<<<(nq + 255) / 256, 256>>>((float4*)out, nq);
}

// round 15
// speedup vs baseline: 1.1959x; 1.1959x over previous
#include <cuda_runtime.h>
#include <cuda_bf16.h>
#include <cstdint>

#define F 128
#define RCUT 5.0f
#define MAX_NODES 100000
#define NODE_GRID 296

// Scratch (allocation-free rule: __device__ globals)
__device__ float  q_dev[MAX_NODES];
__device__ float4 mu4_dev[MAX_NODES];
// Transposed split-bf16 W1 images: W1T[f][k], dense [128][128] bf16
__device__ __align__(16) unsigned char W1T_hi[32768];
__device__ __align__(16) unsigned char W1T_lo[32768];

static __device__ __forceinline__ float silu_f(float z) {
    return __fdividef(z, 1.0f + __expf(-z));
}
static __device__ __forceinline__ uint32_t bpack(__nv_bfloat16 lo, __nv_bfloat16 hi) {
    return (uint32_t)__bfloat16_as_ushort(lo) | ((uint32_t)__bfloat16_as_ushort(hi) << 16);
}
static __device__ __forceinline__ uint32_t smem_u32(const void* p) {
    uint32_t a;
    asm("{ .reg .u64 t; cvta.to.shared.u64 t, %1; cvt.u32.u64 %0, t; }" : "=r"(a) : "l"(p));
    return a;
}

// warp-level bf16 MMA, baseline ISA (works on plain sm_103 target)
static __device__ __forceinline__ void mma16816(float* d, const uint32_t* a,
                                                uint32_t b0, uint32_t b1) {
    asm volatile(
        "mma.sync.aligned.m16n8k16.row.col.f32.bf16.bf16.f32 "
        "{%0,%1,%2,%3}, {%4,%5,%6,%7}, {%8,%9}, {%0,%1,%2,%3};"
        : "+f"(d[0]), "+f"(d[1]), "+f"(d[2]), "+f"(d[3])
        : "r"(a[0]), "r"(a[1]), "r"(a[2]), "r"(a[3]), "r"(b0), "r"(b1));
}
static __device__ __forceinline__ void ldsm4(uint32_t* r, uint32_t addr) {
    asm volatile("ldmatrix.sync.aligned.m8n8.x4.shared.b16 {%0,%1,%2,%3}, [%4];"
                 : "=r"(r[0]), "=r"(r[1]), "=r"(r[2]), "=r"(r[3]) : "r"(addr));
}

// ---------- Kernel 0: W1 -> transposed split-bf16 images ----------
__global__ void prep_B_kernel(const float* __restrict__ W1) {
    const int f = threadIdx.x;
    const int b = blockIdx.x;
    uint32_t hi[4], lo[4];
    #pragma unroll
    for (int j = 0; j < 4; j++) {
        const float w0 = W1[(8 * b + 2 * j)     * F + f];
        const float w1 = W1[(8 * b + 2 * j + 1) * F + f];
        const __nv_bfloat16 h0 = __float2bfloat16_rn(w0);
        const __nv_bfloat16 h1 = __float2bfloat16_rn(w1);
        const __nv_bfloat16 l0 = __float2bfloat16_rn(w0 - __bfloat162float(h0));
        const __nv_bfloat16 l1 = __float2bfloat16_rn(w1 - __bfloat162float(h1));
        hi[j] = bpack(h0, h1);
        lo[j] = bpack(l0, l1);
    }
    *(uint4*)(W1T_hi + f * 256 + b * 16) = make_uint4(hi[0], hi[1], hi[2], hi[3]);
    *(uint4*)(W1T_lo + f * 256 + b * 16) = make_uint4(lo[0], lo[1], lo[2], lo[3]);
}

// ---------- Kernel 1: persistent node MLP, pipelined split-bf16 mma.sync ----
#define PADB 272
#define SM_AH  0
#define SM_AL  17408
#define SM_BH  34816
#define SM_BL  69632
#define SM_B1  104448
#define SM_W2  104960
#define SM_RED 105472
#define SM_TOT 106496

static __device__ __forceinline__ void load_xtile(float4* xreg, const float* __restrict__ x,
                                                  int tile, int n_tiles, int n_nodes, int tid) {
    const int base = tile * 64;
    #pragma unroll
    for (int j = 0; j < 8; j++) {
        const int i   = tid + j * 256;
        const int row = i >> 5;
        const int c4  = i & 31;
        xreg[j] = make_float4(0.f, 0.f, 0.f, 0.f);
        if (tile < n_tiles && base + row < n_nodes)
            xreg[j] = ((const float4*)(x + (size_t)(base + row) * F))[c4];
    }
}
static __device__ __forceinline__ void store_xtile(unsigned char* smem, const float4* xreg,
                                                   int tid) {
    #pragma unroll
    for (int j = 0; j < 8; j++) {
        const int i   = tid + j * 256;
        const int row = i >> 5;
        const int col = 4 * (i & 31);
        const float4 v = xreg[j];
        const __nv_bfloat16 h0 = __float2bfloat16_rn(v.x);
        const __nv_bfloat16 h1 = __float2bfloat16_rn(v.y);
        const __nv_bfloat16 h2 = __float2bfloat16_rn(v.z);
        const __nv_bfloat16 h3 = __float2bfloat16_rn(v.w);
        const __nv_bfloat16 l0 = __float2bfloat16_rn(v.x - __bfloat162float(h0));
        const __nv_bfloat16 l1 = __float2bfloat16_rn(v.y - __bfloat162float(h1));
        const __nv_bfloat16 l2 = __float2bfloat16_rn(v.z - __bfloat162float(h2));
        const __nv_bfloat16 l3 = __float2bfloat16_rn(v.w - __bfloat162float(h3));
        const int off = row * PADB + col * 2;
        *(uint2*)(smem + SM_AH + off) = make_uint2(bpack(h0, h1), bpack(h2, h3));
        *(uint2*)(smem + SM_AL + off) = make_uint2(bpack(l0, l1), bpack(l2, l3));
    }
}

__global__ void __launch_bounds__(256, 2)
node_q_kernel(const float* __restrict__ x, const float* __restrict__ b1,
              const float* __restrict__ W2, const float* __restrict__ b2,
              int n_nodes) {
    extern __shared__ __align__(16) unsigned char smem[];
    const uint32_t sb = smem_u32(smem);
    const int tid  = threadIdx.x;
    const int wid  = tid >> 5;
    const int lane = tid & 31;
    const int g    = lane >> 2;
    const int qp   = lane & 3;
    const int mi   = wid & 1;     // 32-node subtile
    const int nj   = wid >> 1;    // 32-feature subtile
    const int n_tiles = (n_nodes + 63) / 64;

    // Zero accumulation scratch (edge kernel is ordered after us)
    for (int i = blockIdx.x * 256 + tid; i < n_nodes; i += NODE_GRID * 256)
        mu4_dev[i] = make_float4(0.f, 0.f, 0.f, 0.f);

    // ---- Stage B images ONCE per CTA ----
    for (int i = tid; i < 4096; i += 256) {
        const int row = i >> 5;
        const int c4  = i & 31;
        const int goff = row * 256 + c4 * 8;
        const int soff = row * PADB + c4 * 8;
        *(uint2*)(smem + SM_BH + soff) = *(const uint2*)(W1T_hi + goff);
        *(uint2*)(smem + SM_BL + soff) = *(const uint2*)(W1T_lo + goff);
    }
    if (tid < 128) {
        ((float*)(smem + SM_B1))[tid] = b1[tid];
        ((float*)(smem + SM_W2))[tid] = W2[tid];
    }

    // ldmatrix per-thread offsets
    const int lr = lane & 7;
    const uint32_t aoff = (uint32_t)(32 * mi + lr + 8 * ((lane >> 3) & 1)) * PADB
                        + 16 * (lane >> 4);
    const uint32_t boff = (uint32_t)(32 * nj + lr + 8 * (lane >> 4)) * PADB
                        + 16 * ((lane >> 3) & 1);

    const float* b1s = (const float*)(smem + SM_B1);
    const float* w2s = (const float*)(smem + SM_W2);
    float* red = (float*)(smem + SM_RED);   // [4 nj][64 rows]
    const float b2v = b2[0];

    // ---- Pipeline prologue ----
    float4 xreg[8];
    int t = blockIdx.x;
    load_xtile(xreg, x, t, n_tiles, n_nodes, tid);
    store_xtile(smem, xreg, tid);
    load_xtile(xreg, x, t + NODE_GRID, n_tiles, n_nodes, tid);
    __syncthreads();

    for (; t < n_tiles; t += NODE_GRID) {
        // ---- Fused 3-term MMA over current A tile ----
        float acc[2][4][4];
        #pragma unroll
        for (int mc = 0; mc < 2; mc++)
            #pragma unroll
            for (int nc = 0; nc < 4; nc++)
                #pragma unroll
                for (int r = 0; r < 4; r++) acc[mc][nc][r] = 0.0f;

        #pragma unroll
        for (int kc = 0; kc < 8; kc++) {
            const uint32_t kb = kc * 32;
            uint32_t ah[2][4], al[2][4];
            ldsm4(ah[0], sb + SM_AH + aoff + kb);
            ldsm4(ah[1], sb + SM_AH + aoff + 16 * PADB + kb);
            ldsm4(al[0], sb + SM_AL + aoff + kb);
            ldsm4(al[1], sb + SM_AL + aoff + 16 * PADB + kb);
            #pragma unroll
            for (int c = 0; c < 2; c++) {
                uint32_t bh[4], bl[4];
                ldsm4(bh, sb + SM_BH + boff + c * 16 * PADB + kb);
                ldsm4(bl, sb + SM_BL + boff + c * 16 * PADB + kb);
                #pragma unroll
                for (int h = 0; h < 2; h++) {
                    const int nc = 2 * c + h;
                    #pragma unroll
                    for (int mc = 0; mc < 2; mc++) {
                        mma16816(acc[mc][nc], ah[mc], bh[2 * h], bh[2 * h + 1]); // xh@Wh
                        mma16816(acc[mc][nc], al[mc], bh[2 * h], bh[2 * h + 1]); // xl@Wh
                        mma16816(acc[mc][nc], ah[mc], bl[2 * h], bl[2 * h + 1]); // xh@Wl
                    }
                }
            }
        }

        // ---- Epilogue: partial q over this warp's 32 features ----
        #pragma unroll
        for (int mc = 0; mc < 2; mc++) {
            #pragma unroll
            for (int rh = 0; rh < 2; rh++) {
                float s = 0.0f;
                #pragma unroll
                for (int nc = 0; nc < 4; nc++) {
                    const int f0 = 32 * nj + 8 * nc + 2 * qp;
                    const float h0 = acc[mc][nc][2 * rh]     + b1s[f0];
                    const float h1 = acc[mc][nc][2 * rh + 1] + b1s[f0 + 1];
                    s += silu_f(h0) * w2s[f0] + silu_f(h1) * w2s[f0 + 1];
                }
                s += __shfl_xor_sync(0xffffffffu, s, 1);
                s += __shfl_xor_sync(0xffffffffu, s, 2);
                if (qp == 0)
                    red[nj * 64 + 32 * mi + 16 * mc + 8 * rh + g] = s;
            }
        }
        __syncthreads();   // red ready; all warps done reading A
        const int base = t * 64;
        if (tid < 64 && base + tid < n_nodes) {
            const float sum = (red[tid] + red[64 + tid]) + (red[128 + tid] + red[192 + tid]);
            q_dev[base + tid] = silu_f(sum + b2v);
        }

        // ---- Stage next tile (regs -> smem), prefetch tile after next ----
        store_xtile(smem, xreg, tid);
        load_xtile(xreg, x, t + 2 * NODE_GRID, n_tiles, n_nodes, tid);
        __syncthreads();   // A(t+G) ready; red consumed
    }
}

// ---------- Kernel 2: edge pass, 8 edges/thread, one RED.128 per edge ------
// Per thread: 2 LDG.128 rij + 2 src + 2 dst + 6 vij (16 front-batched loads,
// deep MLP) + 8 scalar q gathers + 8 RED.128.
__global__ void __launch_bounds__(256)
edge_kernel8(const float4* __restrict__ rij4, const float4* __restrict__ vij4,
             const int4* __restrict__ src4, const int4* __restrict__ dst4,
             int n_oct) {
    const int i = blockIdx.x * blockDim.x + threadIdx.x;
    if (i >= n_oct) return;

    const float4 r0 = rij4[2 * i];
    const float4 r1 = rij4[2 * i + 1];
    const int4   s0 = src4[2 * i];
    const int4   s1 = src4[2 * i + 1];
    const int4   d0 = dst4[2 * i];
    const int4   d1 = dst4[2 * i + 1];
    const size_t vb = (size_t)6 * i;
    const float4 va = vij4[vb];
    const float4 vbv = vij4[vb + 1];
    const float4 vc = vij4[vb + 2];
    const float4 vd = vij4[vb + 3];
    const float4 ve = vij4[vb + 4];
    const float4 vf = vij4[vb + 5];

    const float k = 3.14159265358979323846f / RCUT;
    float c0 = 0.5f * (__cosf(r0.x * k) + 1.0f); if (r0.x >= RCUT) c0 = 0.0f;
    float c1 = 0.5f * (__cosf(r0.y * k) + 1.0f); if (r0.y >= RCUT) c1 = 0.0f;
    float c2 = 0.5f * (__cosf(r0.z * k) + 1.0f); if (r0.z >= RCUT) c2 = 0.0f;
    float c3 = 0.5f * (__cosf(r0.w * k) + 1.0f); if (r0.w >= RCUT) c3 = 0.0f;
    float c4 = 0.5f * (__cosf(r1.x * k) + 1.0f); if (r1.x >= RCUT) c4 = 0.0f;
    float c5 = 0.5f * (__cosf(r1.y * k) + 1.0f); if (r1.y >= RCUT) c5 = 0.0f;
    float c6 = 0.5f * (__cosf(r1.z * k) + 1.0f); if (r1.z >= RCUT) c6 = 0.0f;
    float c7 = 0.5f * (__cosf(r1.w * k) + 1.0f); if (r1.w >= RCUT) c7 = 0.0f;

    const float t0 = __ldg(&q_dev[s0.x]) * c0;
    const float t1 = __ldg(&q_dev[s0.y]) * c1;
    const float t2 = __ldg(&q_dev[s0.z]) * c2;
    const float t3 = __ldg(&q_dev[s0.w]) * c3;
    const float t4 = __ldg(&q_dev[s1.x]) * c4;
    const float t5 = __ldg(&q_dev[s1.y]) * c5;
    const float t6 = __ldg(&q_dev[s1.z]) * c6;
    const float t7 = __ldg(&q_dev[s1.w]) * c7;

    atomicAdd(&mu4_dev[d0.x], make_float4(va.x * t0, va.y * t0, va.z * t0, 0.0f));
    atomicAdd(&mu4_dev[d0.y], make_float4(va.w * t1, vbv.x * t1, vbv.y * t1, 0.0f));
    atomicAdd(&mu4_dev[d0.z], make_float4(vbv.z * t2, vbv.w * t2, vc.x * t2, 0.0f));
    atomicAdd(&mu4_dev[d0.w], make_float4(vc.y * t3, vc.z * t3, vc.w * t3, 0.0f));
    atomicAdd(&mu4_dev[d1.x], make_float4(vd.x * t4, vd.y * t4, vd.z * t4, 0.0f));
    atomicAdd(&mu4_dev[d1.y], make_float4(vd.w * t5, ve.x * t5, ve.y * t5, 0.0f));
    atomicAdd(&mu4_dev[d1.z], make_float4(ve.z * t6, ve.w * t6, vf.x * t6, 0.0f));
    atomicAdd(&mu4_dev[d1.w], make_float4(vf.y * t7, vf.z * t7, vf.w * t7, 0.0f));
}

// ---------- Kernel 3: compact [N,4] scratch -> [N,3] output, 4 nodes/thread --
__global__ void copy_kernel4(float4* __restrict__ out4, int n_quads) {
    const int i = blockIdx.x * blockDim.x + threadIdx.x;
    if (i >= n_quads) return;
    const float4 m0 = mu4_dev[4 * i];
    const float4 m1 = mu4_dev[4 * i + 1];
    const float4 m2 = mu4_dev[4 * i + 2];
    const float4 m3 = mu4_dev[4 * i + 3];
    out4[3 * i]     = make_float4(m0.x, m0.y, m0.z, m1.x);
    out4[3 * i + 1] = make_float4(m1.y, m1.z, m2.x, m2.y);
    out4[3 * i + 2] = make_float4(m2.z, m3.x, m3.y, m3.z);
}

extern "C" void kernel_launch(void* const* d_in, const int* in_sizes, int n_in,
                              void* d_out, int out_size) {
    const float* x   = (const float*)d_in[0];
    const float* rij = (const float*)d_in[1];
    const float* vij = (const float*)d_in[2];
    const int*   src = (const int*)d_in[3];
    const int*   dst = (const int*)d_in[4];
    const float* W1  = (const float*)d_in[5];
    const float* b1  = (const float*)d_in[6];
    const float* W2  = (const float*)d_in[7];
    const float* b2  = (const float*)d_in[8];
    float* out = (float*)d_out;

    const int n_nodes = in_sizes[0] / F;   // 100000
    const int n_edges = in_sizes[1];       // 6400000

    cudaFuncSetAttribute(node_q_kernel,
                         cudaFuncAttributeMaxDynamicSharedMemorySize, SM_TOT);

    prep_B_kernel<<<16, 128>>>(W1);

    node_q_kernel<<<NODE_GRID, 256, SM_TOT>>>(x, b1, W2, b2, n_nodes);

    const int eo = n_edges / 8;            // 800,000 (exact)
    edge_kernel8<<<(eo + 255) / 256, 256>>>((const float4*)rij, (const float4*)vij,
                                            (const int4*)src, (const int4*)dst, eo);

    const int nq = n_nodes / 4;            // 25,000 (exact)
    copy_kernel4<<<(nq + 255) / 256, 256>>>((float4*)out, nq);
}

// round 16
// speedup vs baseline: 1.3164x; 1.1008x over previous
#include <cuda_runtime.h>
#include <cuda_bf16.h>
#include <cstdint>

#define F 128
#define RCUT 5.0f
#define MAX_NODES 100000
#define NODE_GRID 296

// Scratch (allocation-free rule: __device__ globals)
__device__ float  q_dev[MAX_NODES];
__device__ float4 mu4_dev[MAX_NODES];
// Transposed split-bf16 W1 images: W1T[f][k], dense [128][128] bf16
__device__ __align__(16) unsigned char W1T_hi[32768];
__device__ __align__(16) unsigned char W1T_lo[32768];

static __device__ __forceinline__ float silu_f(float z) {
    return __fdividef(z, 1.0f + __expf(-z));
}
static __device__ __forceinline__ uint32_t bpack(__nv_bfloat16 lo, __nv_bfloat16 hi) {
    return (uint32_t)__bfloat16_as_ushort(lo) | ((uint32_t)__bfloat16_as_ushort(hi) << 16);
}
static __device__ __forceinline__ uint32_t smem_u32(const void* p) {
    uint32_t a;
    asm("{ .reg .u64 t; cvta.to.shared.u64 t, %1; cvt.u32.u64 %0, t; }" : "=r"(a) : "l"(p));
    return a;
}

// warp-level bf16 MMA, baseline ISA (works on plain sm_103 target)
static __device__ __forceinline__ void mma16816(float* d, const uint32_t* a,
                                                uint32_t b0, uint32_t b1) {
    asm volatile(
        "mma.sync.aligned.m16n8k16.row.col.f32.bf16.bf16.f32 "
        "{%0,%1,%2,%3}, {%4,%5,%6,%7}, {%8,%9}, {%0,%1,%2,%3};"
        : "+f"(d[0]), "+f"(d[1]), "+f"(d[2]), "+f"(d[3])
        : "r"(a[0]), "r"(a[1]), "r"(a[2]), "r"(a[3]), "r"(b0), "r"(b1));
}
static __device__ __forceinline__ void ldsm4(uint32_t* r, uint32_t addr) {
    asm volatile("ldmatrix.sync.aligned.m8n8.x4.shared.b16 {%0,%1,%2,%3}, [%4];"
                 : "=r"(r[0]), "=r"(r[1]), "=r"(r[2]), "=r"(r[3]) : "r"(addr));
}

// ---------- Kernel 0: W1 -> transposed split-bf16 images; zero mu4 scratch --
// grid 16 x 128. Block b covers k-rows 8b..8b+7; thread = feature f.
__global__ void prep_B_kernel(const float* __restrict__ W1, int n_nodes) {
    const int f = threadIdx.x;
    const int b = blockIdx.x;
    uint32_t hi[4], lo[4];
    #pragma unroll
    for (int j = 0; j < 4; j++) {
        const float w0 = W1[(8 * b + 2 * j)     * F + f];
        const float w1 = W1[(8 * b + 2 * j + 1) * F + f];
        const __nv_bfloat16 h0 = __float2bfloat16_rn(w0);
        const __nv_bfloat16 h1 = __float2bfloat16_rn(w1);
        const __nv_bfloat16 l0 = __float2bfloat16_rn(w0 - __bfloat162float(h0));
        const __nv_bfloat16 l1 = __float2bfloat16_rn(w1 - __bfloat162float(h1));
        hi[j] = bpack(h0, h1);
        lo[j] = bpack(l0, l1);
    }
    *(uint4*)(W1T_hi + f * 256 + b * 16) = make_uint4(hi[0], hi[1], hi[2], hi[3]);
    *(uint4*)(W1T_lo + f * 256 + b * 16) = make_uint4(lo[0], lo[1], lo[2], lo[3]);
    // Zero the accumulation scratch (node + edge kernels are ordered after us)
    for (int i = b * 128 + f; i < n_nodes; i += 16 * 128)
        mu4_dev[i] = make_float4(0.f, 0.f, 0.f, 0.f);
}

// ---------- Kernel 1: persistent node MLP, pipelined split-bf16 mma.sync ----
#define PADB 272
#define SM_AH  0
#define SM_AL  17408
#define SM_BH  34816
#define SM_BL  69632
#define SM_B1  104448
#define SM_W2  104960
#define SM_RED 105472
#define SM_TOT 106496

static __device__ __forceinline__ void load_xtile(float4* xreg, const float* __restrict__ x,
                                                  int tile, int n_tiles, int n_nodes, int tid) {
    const int base = tile * 64;
    #pragma unroll
    for (int j = 0; j < 8; j++) {
        const int i   = tid + j * 256;
        const int row = i >> 5;
        const int c4  = i & 31;
        xreg[j] = make_float4(0.f, 0.f, 0.f, 0.f);
        if (tile < n_tiles && base + row < n_nodes)
            xreg[j] = ((const float4*)(x + (size_t)(base + row) * F))[c4];
    }
}
static __device__ __forceinline__ void store_xtile(unsigned char* smem, const float4* xreg,
                                                   int tid) {
    #pragma unroll
    for (int j = 0; j < 8; j++) {
        const int i   = tid + j * 256;
        const int row = i >> 5;
        const int col = 4 * (i & 31);
        const float4 v = xreg[j];
        const __nv_bfloat16 h0 = __float2bfloat16_rn(v.x);
        const __nv_bfloat16 h1 = __float2bfloat16_rn(v.y);
        const __nv_bfloat16 h2 = __float2bfloat16_rn(v.z);
        const __nv_bfloat16 h3 = __float2bfloat16_rn(v.w);
        const __nv_bfloat16 l0 = __float2bfloat16_rn(v.x - __bfloat162float(h0));
        const __nv_bfloat16 l1 = __float2bfloat16_rn(v.y - __bfloat162float(h1));
        const __nv_bfloat16 l2 = __float2bfloat16_rn(v.z - __bfloat162float(h2));
        const __nv_bfloat16 l3 = __float2bfloat16_rn(v.w - __bfloat162float(h3));
        const int off = row * PADB + col * 2;
        *(uint2*)(smem + SM_AH + off) = make_uint2(bpack(h0, h1), bpack(h2, h3));
        *(uint2*)(smem + SM_AL + off) = make_uint2(bpack(l0, l1), bpack(l2, l3));
    }
}

__global__ void __launch_bounds__(256, 2)
node_q_kernel(const float* __restrict__ x, const float* __restrict__ b1,
              const float* __restrict__ W2, const float* __restrict__ b2,
              int n_nodes) {
    extern __shared__ __align__(16) unsigned char smem[];
    const uint32_t sb = smem_u32(smem);
    const int tid  = threadIdx.x;
    const int wid  = tid >> 5;
    const int lane = tid & 31;
    const int g    = lane >> 2;
    const int qp   = lane & 3;
    const int mi   = wid & 1;     // 32-node subtile
    const int nj   = wid >> 1;    // 32-feature subtile
    const int n_tiles = (n_nodes + 63) / 64;

    // ---- Stage B images ONCE per CTA ----
    for (int i = tid; i < 4096; i += 256) {
        const int row = i >> 5;
        const int c4  = i & 31;
        const int goff = row * 256 + c4 * 8;
        const int soff = row * PADB + c4 * 8;
        *(uint2*)(smem + SM_BH + soff) = *(const uint2*)(W1T_hi + goff);
        *(uint2*)(smem + SM_BL + soff) = *(const uint2*)(W1T_lo + goff);
    }
    if (tid < 128) {
        ((float*)(smem + SM_B1))[tid] = b1[tid];
        ((float*)(smem + SM_W2))[tid] = W2[tid];
    }

    // ldmatrix per-thread offsets
    const int lr = lane & 7;
    const uint32_t aoff = (uint32_t)(32 * mi + lr + 8 * ((lane >> 3) & 1)) * PADB
                        + 16 * (lane >> 4);
    const uint32_t boff = (uint32_t)(32 * nj + lr + 8 * (lane >> 4)) * PADB
                        + 16 * ((lane >> 3) & 1);

    const float* b1s = (const float*)(smem + SM_B1);
    const float* w2s = (const float*)(smem + SM_W2);
    float* red = (float*)(smem + SM_RED);   // [4 nj][64 rows]
    const float b2v = b2[0];

    // ---- Pipeline prologue ----
    float4 xreg[8];
    int t = blockIdx.x;
    load_xtile(xreg, x, t, n_tiles, n_nodes, tid);
    store_xtile(smem, xreg, tid);
    load_xtile(xreg, x, t + NODE_GRID, n_tiles, n_nodes, tid);
    __syncthreads();

    for (; t < n_tiles; t += NODE_GRID) {
        // ---- Fused 3-term MMA over current A tile ----
        float acc[2][4][4];
        #pragma unroll
        for (int mc = 0; mc < 2; mc++)
            #pragma unroll
            for (int nc = 0; nc < 4; nc++)
                #pragma unroll
                for (int r = 0; r < 4; r++) acc[mc][nc][r] = 0.0f;

        #pragma unroll
        for (int kc = 0; kc < 8; kc++) {
            const uint32_t kb = kc * 32;
            uint32_t ah[2][4], al[2][4];
            ldsm4(ah[0], sb + SM_AH + aoff + kb);
            ldsm4(ah[1], sb + SM_AH + aoff + 16 * PADB + kb);
            ldsm4(al[0], sb + SM_AL + aoff + kb);
            ldsm4(al[1], sb + SM_AL + aoff + 16 * PADB + kb);
            #pragma unroll
            for (int c = 0; c < 2; c++) {
                uint32_t bh[4], bl[4];
                ldsm4(bh, sb + SM_BH + boff + c * 16 * PADB + kb);
                ldsm4(bl, sb + SM_BL + boff + c * 16 * PADB + kb);
                #pragma unroll
                for (int h = 0; h < 2; h++) {
                    const int nc = 2 * c + h;
                    #pragma unroll
                    for (int mc = 0; mc < 2; mc++) {
                        mma16816(acc[mc][nc], ah[mc], bh[2 * h], bh[2 * h + 1]); // xh@Wh
                        mma16816(acc[mc][nc], al[mc], bh[2 * h], bh[2 * h + 1]); // xl@Wh
                        mma16816(acc[mc][nc], ah[mc], bl[2 * h], bl[2 * h + 1]); // xh@Wl
                    }
                }
            }
        }

        // ---- Epilogue: partial q over this warp's 32 features ----
        #pragma unroll
        for (int mc = 0; mc < 2; mc++) {
            #pragma unroll
            for (int rh = 0; rh < 2; rh++) {
                float s = 0.0f;
                #pragma unroll
                for (int nc = 0; nc < 4; nc++) {
                    const int f0 = 32 * nj + 8 * nc + 2 * qp;
                    const float h0 = acc[mc][nc][2 * rh]     + b1s[f0];
                    const float h1 = acc[mc][nc][2 * rh + 1] + b1s[f0 + 1];
                    s += silu_f(h0) * w2s[f0] + silu_f(h1) * w2s[f0 + 1];
                }
                s += __shfl_xor_sync(0xffffffffu, s, 1);
                s += __shfl_xor_sync(0xffffffffu, s, 2);
                if (qp == 0)
                    red[nj * 64 + 32 * mi + 16 * mc + 8 * rh + g] = s;
            }
        }
        __syncthreads();   // red ready; all warps done reading A
        const int base = t * 64;
        if (tid < 64 && base + tid < n_nodes) {
            const float sum = (red[tid] + red[64 + tid]) + (red[128 + tid] + red[192 + tid]);
            q_dev[base + tid] = silu_f(sum + b2v);
        }

        // ---- Stage next tile (regs -> smem), prefetch tile after next ----
        store_xtile(smem, xreg, tid);
        load_xtile(xreg, x, t + 2 * NODE_GRID, n_tiles, n_nodes, tid);
        __syncthreads();   // A(t+G) ready; red consumed
    }
}

// ---------- Kernel 2: edge pass, 4 edges/thread, RED.128 per edge ----------
// Streaming loads use __ldcs (evict-first) so the 154 MB stream does not
// evict the L2-hot q_dev / mu4_dev lines hit by the random gathers/REDs.
__global__ void __launch_bounds__(256)
edge_kernel4(const float4* __restrict__ rij4, const float4* __restrict__ vij4,
             const int4* __restrict__ src4, const int4* __restrict__ dst4,
             int n_quads) {
    const int i = blockIdx.x * blockDim.x + threadIdx.x;
    if (i >= n_quads) return;

    const float4 r = __ldcs(rij4 + i);
    const int4   s = __ldcs(src4 + i);
    const int4   d = __ldcs(dst4 + i);
    const float4 a = __ldcs(vij4 + (size_t)3 * i);
    const float4 b = __ldcs(vij4 + (size_t)3 * i + 1);
    const float4 c = __ldcs(vij4 + (size_t)3 * i + 2);

    const float k = 3.14159265358979323846f / RCUT;
    float c0 = 0.5f * (__cosf(r.x * k) + 1.0f); if (r.x >= RCUT) c0 = 0.0f;
    float c1 = 0.5f * (__cosf(r.y * k) + 1.0f); if (r.y >= RCUT) c1 = 0.0f;
    float c2 = 0.5f * (__cosf(r.z * k) + 1.0f); if (r.z >= RCUT) c2 = 0.0f;
    float c3 = 0.5f * (__cosf(r.w * k) + 1.0f); if (r.w >= RCUT) c3 = 0.0f;

    const float s0 = __ldg(&q_dev[s.x]) * c0;
    const float s1 = __ldg(&q_dev[s.y]) * c1;
    const float s2 = __ldg(&q_dev[s.z]) * c2;
    const float s3 = __ldg(&q_dev[s.w]) * c3;

    atomicAdd(&mu4_dev[d.x], make_float4(a.x * s0, a.y * s0, a.z * s0, 0.0f));
    atomicAdd(&mu4_dev[d.y], make_float4(a.w * s1, b.x * s1, b.y * s1, 0.0f));
    atomicAdd(&mu4_dev[d.z], make_float4(b.z * s2, b.w * s2, c.x * s2, 0.0f));
    atomicAdd(&mu4_dev[d.w], make_float4(c.y * s3, c.z * s3, c.w * s3, 0.0f));
}

// ---------- Kernel 3: compact [N,4] scratch -> [N,3] output, 4 nodes/thread --
__global__ void copy_kernel4(float4* __restrict__ out4, int n_quads) {
    const int i = blockIdx.x * blockDim.x + threadIdx.x;
    if (i >= n_quads) return;
    const float4 m0 = mu4_dev[4 * i];
    const float4 m1 = mu4_dev[4 * i + 1];
    const float4 m2 = mu4_dev[4 * i + 2];
    const float4 m3 = mu4_dev[4 * i + 3];
    out4[3 * i]     = make_float4(m0.x, m0.y, m0.z, m1.x);
    out4[3 * i + 1] = make_float4(m1.y, m1.z, m2.x, m2.y);
    out4[3 * i + 2] = make_float4(m2.z, m3.x, m3.y, m3.z);
}

extern "C" void kernel_launch(void* const* d_in, const int* in_sizes, int n_in,
                              void* d_out, int out_size) {
    const float* x   = (const float*)d_in[0];
    const float* rij = (const float*)d_in[1];
    const float* vij = (const float*)d_in[2];
    const int*   src = (const int*)d_in[3];
    const int*   dst = (const int*)d_in[4];
    const float* W1  = (const float*)d_in[5];
    const float* b1  = (const float*)d_in[6];
    const float* W2  = (const float*)d_in[7];
    const float* b2  = (const float*)d_in[8];
    float* out = (float*)d_out;

    const int n_nodes = in_sizes[0] / F;   // 100000
    const int n_edges = in_sizes[1];       // 6400000

    cudaFuncSetAttribute(node_q_kernel,
                         cudaFuncAttributeMaxDynamicSharedMemorySize, SM_TOT);

    prep_B_kernel<<<16, 128>>>(W1, n_nodes);

    node_q_kernel<<<NODE_GRID, 256, SM_TOT>>>(x, b1, W2, b2, n_nodes);

    const int eq = n_edges / 4;            // 1,600,000 (exact)
    edge_kernel4<<<(eq + 255) / 256, 256>>>((const float4*)rij, (const float4*)vij,
                                            (const int4*)src, (const int4*)dst, eq);

    const int nq = n_nodes / 4;            // 25,000 (exact)
    copy_kernel4<<<(nq + 255) / 256, 256>>>((float4*)out, nq);
}

// round 17
// speedup vs baseline: 1.4249x; 1.0824x over previous
#include <cuda_runtime.h>
#include <cuda_bf16.h>
#include <cstdint>

#define F 128
#define RCUT 5.0f
#define MAX_NODES 100000
#define NODE_GRID 296

// Scratch (allocation-free rule: __device__ globals)
__device__ float  q_dev[MAX_NODES];
__device__ float4 mu4_dev[MAX_NODES];

static __device__ __forceinline__ float silu_f(float z) {
    return __fdividef(z, 1.0f + __expf(-z));
}
static __device__ __forceinline__ uint32_t bpack(__nv_bfloat16 lo, __nv_bfloat16 hi) {
    return (uint32_t)__bfloat16_as_ushort(lo) | ((uint32_t)__bfloat16_as_ushort(hi) << 16);
}
static __device__ __forceinline__ uint32_t smem_u32(const void* p) {
    uint32_t a;
    asm("{ .reg .u64 t; cvta.to.shared.u64 t, %1; cvt.u32.u64 %0, t; }" : "=r"(a) : "l"(p));
    return a;
}

// warp-level bf16 MMA, baseline ISA (works on plain sm_103 target)
static __device__ __forceinline__ void mma16816(float* d, const uint32_t* a,
                                                uint32_t b0, uint32_t b1) {
    asm volatile(
        "mma.sync.aligned.m16n8k16.row.col.f32.bf16.bf16.f32 "
        "{%0,%1,%2,%3}, {%4,%5,%6,%7}, {%8,%9}, {%0,%1,%2,%3};"
        : "+f"(d[0]), "+f"(d[1]), "+f"(d[2]), "+f"(d[3])
        : "r"(a[0]), "r"(a[1]), "r"(a[2]), "r"(a[3]), "r"(b0), "r"(b1));
}
static __device__ __forceinline__ void ldsm4(uint32_t* r, uint32_t addr) {
    asm volatile("ldmatrix.sync.aligned.m8n8.x4.shared.b16 {%0,%1,%2,%3}, [%4];"
                 : "=r"(r[0]), "=r"(r[1]), "=r"(r[2]), "=r"(r[3]) : "r"(addr));
}

// ---------- Kernel 1: persistent node MLP, pipelined split-bf16 mma.sync ----
// Grid = 296 persistent CTAs (2/SM), 256 thr / 8 warps, tile = 64 nodes.
// Each CTA converts W1 (fp32, L2-hot) into its own split-bf16 smem images
// ONCE (same math as the old prep kernel — launch eliminated). Per tile,
// next x is prefetched into registers while the current tile's MMA runs.
#define PADB 272
#define SM_AH  0
#define SM_AL  17408
#define SM_BH  34816
#define SM_BL  69632
#define SM_B1  104448
#define SM_W2  104960
#define SM_RED 105472
#define SM_TOT 106496

static __device__ __forceinline__ void load_xtile(float4* xreg, const float* __restrict__ x,
                                                  int tile, int n_tiles, int n_nodes, int tid) {
    const int base = tile * 64;
    #pragma unroll
    for (int j = 0; j < 8; j++) {
        const int i   = tid + j * 256;
        const int row = i >> 5;
        const int c4  = i & 31;
        xreg[j] = make_float4(0.f, 0.f, 0.f, 0.f);
        if (tile < n_tiles && base + row < n_nodes)
            xreg[j] = ((const float4*)(x + (size_t)(base + row) * F))[c4];
    }
}
static __device__ __forceinline__ void store_xtile(unsigned char* smem, const float4* xreg,
                                                   int tid) {
    #pragma unroll
    for (int j = 0; j < 8; j++) {
        const int i   = tid + j * 256;
        const int row = i >> 5;
        const int col = 4 * (i & 31);
        const float4 v = xreg[j];
        const __nv_bfloat16 h0 = __float2bfloat16_rn(v.x);
        const __nv_bfloat16 h1 = __float2bfloat16_rn(v.y);
        const __nv_bfloat16 h2 = __float2bfloat16_rn(v.z);
        const __nv_bfloat16 h3 = __float2bfloat16_rn(v.w);
        const __nv_bfloat16 l0 = __float2bfloat16_rn(v.x - __bfloat162float(h0));
        const __nv_bfloat16 l1 = __float2bfloat16_rn(v.y - __bfloat162float(h1));
        const __nv_bfloat16 l2 = __float2bfloat16_rn(v.z - __bfloat162float(h2));
        const __nv_bfloat16 l3 = __float2bfloat16_rn(v.w - __bfloat162float(h3));
        const int off = row * PADB + col * 2;
        *(uint2*)(smem + SM_AH + off) = make_uint2(bpack(h0, h1), bpack(h2, h3));
        *(uint2*)(smem + SM_AL + off) = make_uint2(bpack(l0, l1), bpack(l2, l3));
    }
}

__global__ void __launch_bounds__(256, 2)
node_q_kernel(const float* __restrict__ x, const float* __restrict__ W1,
              const float* __restrict__ b1, const float* __restrict__ W2,
              const float* __restrict__ b2, int n_nodes) {
    extern __shared__ __align__(16) unsigned char smem[];
    const uint32_t sb = smem_u32(smem);
    const int tid  = threadIdx.x;
    const int wid  = tid >> 5;
    const int lane = tid & 31;
    const int g    = lane >> 2;
    const int qp   = lane & 3;
    const int mi   = wid & 1;     // 32-node subtile
    const int nj   = wid >> 1;    // 32-feature subtile
    const int n_tiles = (n_nodes + 63) / 64;

    // Zero accumulation scratch (edge kernel is ordered after us)
    for (int i = blockIdx.x * 256 + tid; i < n_nodes; i += NODE_GRID * 256)
        mu4_dev[i] = make_float4(0.f, 0.f, 0.f, 0.f);

    // ---- Convert W1 -> transposed split-bf16 smem images (ONCE per CTA) ----
    // B layout: row f (PADB stride), uint32 at k2*4 = bf16 pair (k=2k2, 2k2+1).
    // Same split math as the old prep kernel; W1 reads are lane-coalesced.
    #pragma unroll
    for (int j = 0; j < 8; j++) {
        const int k2 = wid * 8 + j;
        #pragma unroll
        for (int fi = 0; fi < 4; fi++) {
            const int f = lane + 32 * fi;
            const float a0 = W1[(2 * k2) * F + f];
            const float a1 = W1[(2 * k2 + 1) * F + f];
            const __nv_bfloat16 h0 = __float2bfloat16_rn(a0);
            const __nv_bfloat16 h1 = __float2bfloat16_rn(a1);
            const __nv_bfloat16 l0 = __float2bfloat16_rn(a0 - __bfloat162float(h0));
            const __nv_bfloat16 l1 = __float2bfloat16_rn(a1 - __bfloat162float(h1));
            *(uint32_t*)(smem + SM_BH + f * PADB + k2 * 4) = bpack(h0, h1);
            *(uint32_t*)(smem + SM_BL + f * PADB + k2 * 4) = bpack(l0, l1);
        }
    }
    if (tid < 128) {
        ((float*)(smem + SM_B1))[tid] = b1[tid];
        ((float*)(smem + SM_W2))[tid] = W2[tid];
    }

    // ldmatrix per-thread offsets
    const int lr = lane & 7;
    const uint32_t aoff = (uint32_t)(32 * mi + lr + 8 * ((lane >> 3) & 1)) * PADB
                        + 16 * (lane >> 4);
    const uint32_t boff = (uint32_t)(32 * nj + lr + 8 * (lane >> 4)) * PADB
                        + 16 * ((lane >> 3) & 1);

    const float* b1s = (const float*)(smem + SM_B1);
    const float* w2s = (const float*)(smem + SM_W2);
    float* red = (float*)(smem + SM_RED);   // [4 nj][64 rows]
    const float b2v = b2[0];

    // ---- Pipeline prologue ----
    float4 xreg[8];
    int t = blockIdx.x;
    load_xtile(xreg, x, t, n_tiles, n_nodes, tid);
    store_xtile(smem, xreg, tid);
    load_xtile(xreg, x, t + NODE_GRID, n_tiles, n_nodes, tid);
    __syncthreads();

    for (; t < n_tiles; t += NODE_GRID) {
        // ---- Fused 3-term MMA over current A tile ----
        float acc[2][4][4];
        #pragma unroll
        for (int mc = 0; mc < 2; mc++)
            #pragma unroll
            for (int nc = 0; nc < 4; nc++)
                #pragma unroll
                for (int r = 0; r < 4; r++) acc[mc][nc][r] = 0.0f;

        #pragma unroll
        for (int kc = 0; kc < 8; kc++) {
            const uint32_t kb = kc * 32;
            uint32_t ah[2][4], al[2][4];
            ldsm4(ah[0], sb + SM_AH + aoff + kb);
            ldsm4(ah[1], sb + SM_AH + aoff + 16 * PADB + kb);
            ldsm4(al[0], sb + SM_AL + aoff + kb);
            ldsm4(al[1], sb + SM_AL + aoff + 16 * PADB + kb);
            #pragma unroll
            for (int c = 0; c < 2; c++) {
                uint32_t bh[4], bl[4];
                ldsm4(bh, sb + SM_BH + boff + c * 16 * PADB + kb);
                ldsm4(bl, sb + SM_BL + boff + c * 16 * PADB + kb);
                #pragma unroll
                for (int h = 0; h < 2; h++) {
                    const int nc = 2 * c + h;
                    #pragma unroll
                    for (int mc = 0; mc < 2; mc++) {
                        mma16816(acc[mc][nc], ah[mc], bh[2 * h], bh[2 * h + 1]); // xh@Wh
                        mma16816(acc[mc][nc], al[mc], bh[2 * h], bh[2 * h + 1]); // xl@Wh
                        mma16816(acc[mc][nc], ah[mc], bl[2 * h], bl[2 * h + 1]); // xh@Wl
                    }
                }
            }
        }

        // ---- Epilogue: partial q over this warp's 32 features ----
        #pragma unroll
        for (int mc = 0; mc < 2; mc++) {
            #pragma unroll
            for (int rh = 0; rh < 2; rh++) {
                float s = 0.0f;
                #pragma unroll
                for (int nc = 0; nc < 4; nc++) {
                    const int f0 = 32 * nj + 8 * nc + 2 * qp;
                    const float h0 = acc[mc][nc][2 * rh]     + b1s[f0];
                    const float h1 = acc[mc][nc][2 * rh + 1] + b1s[f0 + 1];
                    s += silu_f(h0) * w2s[f0] + silu_f(h1) * w2s[f0 + 1];
                }
                s += __shfl_xor_sync(0xffffffffu, s, 1);
                s += __shfl_xor_sync(0xffffffffu, s, 2);
                if (qp == 0)
                    red[nj * 64 + 32 * mi + 16 * mc + 8 * rh + g] = s;
            }
        }
        __syncthreads();   // red ready; all warps done reading A
        const int base = t * 64;
        if (tid < 64 && base + tid < n_nodes) {
            const float sum = (red[tid] + red[64 + tid]) + (red[128 + tid] + red[192 + tid]);
            q_dev[base + tid] = silu_f(sum + b2v);
        }

        // ---- Stage next tile (regs -> smem), prefetch tile after next ----
        store_xtile(smem, xreg, tid);
        load_xtile(xreg, x, t + 2 * NODE_GRID, n_tiles, n_nodes, tid);
        __syncthreads();   // A(t+G) ready; red consumed
    }
}

// ---------- Kernel 2: edge pass, 4 edges/thread, RED.128 per edge ----------
__global__ void __launch_bounds__(256)
edge_kernel4(const float4* __restrict__ rij4, const float4* __restrict__ vij4,
             const int4* __restrict__ src4, const int4* __restrict__ dst4,
             int n_quads) {
    const int i = blockIdx.x * blockDim.x + threadIdx.x;
    if (i >= n_quads) return;

    const float4 r = __ldcs(rij4 + i);
    const int4   s = __ldcs(src4 + i);
    const int4   d = __ldcs(dst4 + i);
    const float4 a = __ldcs(vij4 + (size_t)3 * i);
    const float4 b = __ldcs(vij4 + (size_t)3 * i + 1);
    const float4 c = __ldcs(vij4 + (size_t)3 * i + 2);

    const float k = 3.14159265358979323846f / RCUT;
    float c0 = 0.5f * (__cosf(r.x * k) + 1.0f); if (r.x >= RCUT) c0 = 0.0f;
    float c1 = 0.5f * (__cosf(r.y * k) + 1.0f); if (r.y >= RCUT) c1 = 0.0f;
    float c2 = 0.5f * (__cosf(r.z * k) + 1.0f); if (r.z >= RCUT) c2 = 0.0f;
    float c3 = 0.5f * (__cosf(r.w * k) + 1.0f); if (r.w >= RCUT) c3 = 0.0f;

    const float s0 = __ldg(&q_dev[s.x]) * c0;
    const float s1 = __ldg(&q_dev[s.y]) * c1;
    const float s2 = __ldg(&q_dev[s.z]) * c2;
    const float s3 = __ldg(&q_dev[s.w]) * c3;

    atomicAdd(&mu4_dev[d.x], make_float4(a.x * s0, a.y * s0, a.z * s0, 0.0f));
    atomicAdd(&mu4_dev[d.y], make_float4(a.w * s1, b.x * s1, b.y * s1, 0.0f));
    atomicAdd(&mu4_dev[d.z], make_float4(b.z * s2, b.w * s2, c.x * s2, 0.0f));
    atomicAdd(&mu4_dev[d.w], make_float4(c.y * s3, c.z * s3, c.w * s3, 0.0f));
}

// ---------- Kernel 3: compact [N,4] scratch -> [N,3] output, 4 nodes/thread --
__global__ void copy_kernel4(float4* __restrict__ out4, int n_quads) {
    const int i = blockIdx.x * blockDim.x + threadIdx.x;
    if (i >= n_quads) return;
    const float4 m0 = mu4_dev[4 * i];
    const float4 m1 = mu4_dev[4 * i + 1];
    const float4 m2 = mu4_dev[4 * i + 2];
    const float4 m3 = mu4_dev[4 * i + 3];
    out4[3 * i]     = make_float4(m0.x, m0.y, m0.z, m1.x);
    out4[3 * i + 1] = make_float4(m1.y, m1.z, m2.x, m2.y);
    out4[3 * i + 2] = make_float4(m2.z, m3.x, m3.y, m3.z);
}

extern "C" void kernel_launch(void* const* d_in, const int* in_sizes, int n_in,
                              void* d_out, int out_size) {
    const float* x   = (const float*)d_in[0];
    const float* rij = (const float*)d_in[1];
    const float* vij = (const float*)d_in[2];
    const int*   src = (const int*)d_in[3];
    const int*   dst = (const int*)d_in[4];
    const float* W1  = (const float*)d_in[5];
    const float* b1  = (const float*)d_in[6];
    const float* W2  = (const float*)d_in[7];
    const float* b2  = (const float*)d_in[8];
    float* out = (float*)d_out;

    const int n_nodes = in_sizes[0] / F;   // 100000
    const int n_edges = in_sizes[1];       // 6400000

    cudaFuncSetAttribute(node_q_kernel,
                         cudaFuncAttributeMaxDynamicSharedMemorySize, SM_TOT);

    node_q_kernel<<<NODE_GRID, 256, SM_TOT>>>(x, W1, b1, W2, b2, n_nodes);

    const int eq = n_edges / 4;            // 1,600,000 (exact)
    edge_kernel4<<<(eq + 255) / 256, 256>>>((const float4*)rij, (const float4*)vij,
                                            (const int4*)src, (const int4*)dst, eq);

    const int nq = n_nodes / 4;            // 25,000 (exact)
    copy_kernel4<<<(nq + 255) / 256, 256>>>((float4*)out, nq);
}